// round 2
// baseline (speedup 1.0000x reference)
#include <cuda_runtime.h>

#define BN_EPS 1e-3f

// ---------------- scratch (device globals, no allocation) ----------------
__device__ __align__(16) float g_a1[16*128*128*8];   // conv1+pool out  (8 MB)
__device__ __align__(16) float g_a2[16*64*64*16];    // conv2+pool out  (4 MB)
__device__ __align__(16) float g_xi[16*32*32*32];    // conv3+pool out, ch-padded: slot0=0, ch c at c+1 (2 MB)
__device__ float g_f1[16*64];                        // d1 pre-bias accumulators
__device__ float g_theta[16*6];                      // affine params

#define FMA4(A, s, W) { A.x += (s)*(W).x; A.y += (s)*(W).y; A.z += (s)*(W).z; A.w += (s)*(W).w; }

// ================= conv1 (1->8) + relu + maxpool2 =================
__global__ void k_conv1(const float* __restrict__ x,
                        const float* __restrict__ w,
                        const float* __restrict__ bias){
  __shared__ float sw[72];
  __shared__ float sb[8];
  int t = threadIdx.x;
  if (t < 72) sw[t] = w[t];
  if (t < 8)  sb[t] = bias[t];
  __syncthreads();
  int id = blockIdx.x*256 + t;                 // 16*128*128 threads
  int px = id & 127, py = (id>>7)&127, bb = id>>14;
  const float* xb = x + bb*65536;
  float in[4][4];
  #pragma unroll
  for (int dy=0; dy<4; dy++){
    int iy = 2*py + dy - 1;
    #pragma unroll
    for (int dx=0; dx<4; dx++){
      int ix = 2*px + dx - 1;
      in[dy][dx] = (iy>=0 && iy<256 && ix>=0 && ix<256) ? xb[iy*256+ix] : 0.f;
    }
  }
  float acc[2][2][8];
  #pragma unroll
  for (int p=0;p<2;p++)
    #pragma unroll
    for (int q=0;q<2;q++)
      #pragma unroll
      for (int oc=0;oc<8;oc++) acc[p][q][oc]=0.f;
  #pragma unroll
  for (int ky=0;ky<3;ky++){
    #pragma unroll
    for (int kx=0;kx<3;kx++){
      float wv[8];
      #pragma unroll
      for (int oc=0;oc<8;oc++) wv[oc] = sw[(ky*3+kx)*8+oc];
      #pragma unroll
      for (int p=0;p<2;p++){
        #pragma unroll
        for (int q=0;q<2;q++){
          float v = in[p+ky][q+kx];
          #pragma unroll
          for (int oc=0;oc<8;oc++) acc[p][q][oc] += v*wv[oc];
        }
      }
    }
  }
  float o[8];
  #pragma unroll
  for (int oc=0;oc<8;oc++){
    float m = fmaxf(fmaxf(acc[0][0][oc],acc[0][1][oc]),
                    fmaxf(acc[1][0][oc],acc[1][1][oc]));
    o[oc] = fmaxf(m + sb[oc], 0.f);
  }
  float4* dst = (float4*)&g_a1[(size_t)id*8];
  dst[0] = make_float4(o[0],o[1],o[2],o[3]);
  dst[1] = make_float4(o[4],o[5],o[6],o[7]);
}

// ================= conv2 (8->16) + relu + maxpool2 =================
// thread = (b, py, px, oc-chunk of 4); 4 chunks.
__global__ void k_conv2(const float* __restrict__ w, const float* __restrict__ bias){
  __shared__ __align__(16) float sw[1152];     // [tap][ic][oc]
  __shared__ __align__(16) float sb[16];
  int t = threadIdx.x;
  for (int i=t; i<1152; i+=256) sw[i] = w[i];
  if (t < 16) sb[t] = bias[t];
  __syncthreads();
  int id = blockIdx.x*256 + t;                 // 4*16*64*64 = 262144 threads
  int px = id & 63, py = (id>>6)&63, bb = (id>>12)&15, ch = id>>16;
  float4 acc00 = make_float4(0,0,0,0), acc01 = acc00, acc10 = acc00, acc11 = acc00;
  for (int ky=0; ky<3; ky++){
    for (int kx=0; kx<3; kx++){
      float pixv[2][2][8];
      #pragma unroll
      for (int p=0;p<2;p++){
        #pragma unroll
        for (int q=0;q<2;q++){
          int iy = 2*py + p + ky - 1;
          int ix = 2*px + q + kx - 1;
          float4 lo = make_float4(0,0,0,0), hi = lo;
          if (iy>=0 && iy<128 && ix>=0 && ix<128){
            const float4* pp = (const float4*)&g_a1[(size_t)(((bb*128+iy)*128+ix))*8];
            lo = pp[0]; hi = pp[1];
          }
          pixv[p][q][0]=lo.x; pixv[p][q][1]=lo.y; pixv[p][q][2]=lo.z; pixv[p][q][3]=lo.w;
          pixv[p][q][4]=hi.x; pixv[p][q][5]=hi.y; pixv[p][q][6]=hi.z; pixv[p][q][7]=hi.w;
        }
      }
      const float4* wrow = (const float4*)&sw[(ky*3+kx)*128 + ch*4];
      #pragma unroll
      for (int ic=0; ic<8; ic++){
        float4 wv = wrow[ic*4];
        FMA4(acc00, pixv[0][0][ic], wv);
        FMA4(acc01, pixv[0][1][ic], wv);
        FMA4(acc10, pixv[1][0][ic], wv);
        FMA4(acc11, pixv[1][1][ic], wv);
      }
    }
  }
  float4 bv = *(const float4*)&sb[ch*4];
  float4 m;
  m.x = fmaxf(fmaxf(fmaxf(acc00.x,acc01.x),fmaxf(acc10.x,acc11.x)) + bv.x, 0.f);
  m.y = fmaxf(fmaxf(fmaxf(acc00.y,acc01.y),fmaxf(acc10.y,acc11.y)) + bv.y, 0.f);
  m.z = fmaxf(fmaxf(fmaxf(acc00.z,acc01.z),fmaxf(acc10.z,acc11.z)) + bv.z, 0.f);
  m.w = fmaxf(fmaxf(fmaxf(acc00.w,acc01.w),fmaxf(acc10.w,acc11.w)) + bv.w, 0.f);
  *(float4*)&g_a2[(size_t)(((bb*64+py)*64+px))*16 + ch*4] = m;
}

// ================= conv3 (16->31) + relu + maxpool2 =================
// thread = (b, py, px, oc-chunk of 4); 8 chunks (oc padded to 32).
__global__ void k_conv3(const float* __restrict__ w, const float* __restrict__ bias){
  __shared__ __align__(16) float sw[4608];     // [tap][ic][ocpad=32]
  __shared__ __align__(16) float sb[32];
  int t = threadIdx.x;
  for (int i=t; i<4608; i+=256){
    int tap_ic = i >> 5, oc = i & 31;
    sw[i] = (oc < 31) ? w[tap_ic*31 + oc] : 0.f;
  }
  if (t < 32) sb[t] = (t < 31) ? bias[t] : 0.f;
  if (blockIdx.x == 0){                         // zero d1 accumulators for this launch
    for (int i=t; i<1024; i+=256) g_f1[i] = 0.f;
  }
  __syncthreads();
  int id = blockIdx.x*256 + t;                  // 8*16*32*32 = 131072 threads
  int px = id & 31, py = (id>>5)&31, bb = (id>>10)&15, ch = id>>14;
  float4 acc00 = make_float4(0,0,0,0), acc01 = acc00, acc10 = acc00, acc11 = acc00;
  for (int ky=0; ky<3; ky++){
    for (int kx=0; kx<3; kx++){
      float pixv[2][2][16];
      #pragma unroll
      for (int p=0;p<2;p++){
        #pragma unroll
        for (int q=0;q<2;q++){
          int iy = 2*py + p + ky - 1;
          int ix = 2*px + q + kx - 1;
          float4 v0 = make_float4(0,0,0,0), v1 = v0, v2 = v0, v3 = v0;
          if (iy>=0 && iy<64 && ix>=0 && ix<64){
            const float4* pp = (const float4*)&g_a2[(size_t)(((bb*64+iy)*64+ix))*16];
            v0 = pp[0]; v1 = pp[1]; v2 = pp[2]; v3 = pp[3];
          }
          pixv[p][q][0]=v0.x;  pixv[p][q][1]=v0.y;  pixv[p][q][2]=v0.z;  pixv[p][q][3]=v0.w;
          pixv[p][q][4]=v1.x;  pixv[p][q][5]=v1.y;  pixv[p][q][6]=v1.z;  pixv[p][q][7]=v1.w;
          pixv[p][q][8]=v2.x;  pixv[p][q][9]=v2.y;  pixv[p][q][10]=v2.z; pixv[p][q][11]=v2.w;
          pixv[p][q][12]=v3.x; pixv[p][q][13]=v3.y; pixv[p][q][14]=v3.z; pixv[p][q][15]=v3.w;
        }
      }
      const float4* wrow = (const float4*)&sw[(ky*3+kx)*512 + ch*4];
      #pragma unroll
      for (int ic=0; ic<16; ic++){
        float4 wv = wrow[ic*8];
        FMA4(acc00, pixv[0][0][ic], wv);
        FMA4(acc01, pixv[0][1][ic], wv);
        FMA4(acc10, pixv[1][0][ic], wv);
        FMA4(acc11, pixv[1][1][ic], wv);
      }
    }
  }
  float mv[4];
  mv[0] = fmaxf(fmaxf(fmaxf(acc00.x,acc01.x),fmaxf(acc10.x,acc11.x)) + sb[ch*4+0], 0.f);
  mv[1] = fmaxf(fmaxf(fmaxf(acc00.y,acc01.y),fmaxf(acc10.y,acc11.y)) + sb[ch*4+1], 0.f);
  mv[2] = fmaxf(fmaxf(fmaxf(acc00.z,acc01.z),fmaxf(acc10.z,acc11.z)) + sb[ch*4+2], 0.f);
  mv[3] = fmaxf(fmaxf(fmaxf(acc00.w,acc01.w),fmaxf(acc10.w,acc11.w)) + sb[ch*4+3], 0.f);
  int pixbase = ((bb*32+py)*32+px)*32;
  if (ch == 0) g_xi[pixbase] = 0.f;             // channel-0 pad slot
  #pragma unroll
  for (int j=0;j<4;j++){
    int oc = ch*4 + j;
    if (oc < 31) g_xi[pixbase + 1 + oc] = mv[j];
  }
}

// ================= BN-fold + dense1 (31744 -> 64), split-K =================
__global__ void k_d1(const float* __restrict__ gamma, const float* __restrict__ beta,
                     const float* __restrict__ mean,  const float* __restrict__ var,
                     const float* __restrict__ d1k){
  __shared__ float sf[1024];
  __shared__ float sacc[16][64];
  int b  = blockIdx.y;
  int cb = blockIdx.x * 1024;
  int t  = threadIdx.x;
  for (int f=t; f<1024; f+=256){
    int i = cb + f;
    int c = i % 31;
    int rest = i / 31;                          // = y*32 + x
    float v = g_xi[(b*1024 + rest)*32 + 1 + c];
    v = (v - mean[i]) * rsqrtf(var[i] + BN_EPS) * gamma[i] + beta[i];
    sf[f] = v;
  }
  __syncthreads();
  int c4 = t & 15;                              // column group (4 cols)
  int g  = t >> 4;                              // feature group (16 groups)
  const float4* k4 = (const float4*)d1k;
  float4 acc = make_float4(0,0,0,0);
  for (int f=g; f<1024; f+=16){
    float s = sf[f];
    float4 wv = k4[(size_t)(cb+f)*16 + c4];
    FMA4(acc, s, wv);
  }
  *(float4*)&sacc[g][c4*4] = acc;
  __syncthreads();
  if (t < 64){
    float s = 0.f;
    #pragma unroll
    for (int gg=0; gg<16; gg++) s += sacc[gg][t];
    atomicAdd(&g_f1[b*64 + t], s);
  }
}

// ================= dense2 + dense3 -> theta =================
__global__ void k_d23(const float* __restrict__ d1b,
                      const float* __restrict__ d2k, const float* __restrict__ d2b,
                      const float* __restrict__ d3k, const float* __restrict__ d3b){
  __shared__ float s1[64];
  __shared__ float s2[96];
  int b = blockIdx.x, t = threadIdx.x;          // 96 threads
  if (t < 64) s1[t] = fmaxf(g_f1[b*64+t] + d1b[t], 0.f);
  __syncthreads();
  float acc = d2b[t];
  #pragma unroll 8
  for (int k=0;k<64;k++) acc += s1[k]*d2k[k*96+t];
  s2[t] = fmaxf(acc, 0.f);
  __syncthreads();
  if (t < 6){
    float a = d3b[t];
    #pragma unroll 8
    for (int k=0;k<96;k++) a += s2[k]*d3k[k*6+t];
    g_theta[b*6+t] = a;
  }
}

// ================= grid-gen + bilinear sampler + leaky relu =================
// block = one (b, y) row, thread = x. out[b,y,x,0..31].
__global__ void k_sample(const float* __restrict__ x, float* __restrict__ out){
  __shared__ float th[6];
  int b = blockIdx.x >> 8;
  int y = blockIdx.x & 255;
  int px = threadIdx.x;
  if (px < 6) th[px] = g_theta[b*6+px];
  __syncthreads();
  float gxn = ((float)px / 255.f)*2.f - 1.f;
  float gyn = ((float)y  / 255.f)*2.f - 1.f;
  float tgx = gxn*th[0] + gyn*th[3] + th[2];
  float tgy = gxn*th[1] + gyn*th[4] + th[5];
  float fx = 0.5f*((tgx + 1.f)*255.f);
  float fy = 0.5f*((tgy + 1.f)*255.f);
  float x0 = floorf(fx), x1 = x0 + 1.f;
  float y0 = floorf(fy), y1 = y0 + 1.f;
  x0 = fminf(fmaxf(x0,0.f),255.f);  x1 = fminf(fmaxf(x1,0.f),255.f);
  y0 = fminf(fmaxf(y0,0.f),255.f);  y1 = fminf(fmaxf(y1,0.f),255.f);
  float wa = (x1-fx)*(y1-fy);
  float wb = (x1-fx)*(fy-y0);
  float wc = (fx-x0)*(y1-fy);
  float wd = (fx-x0)*(fy-y0);
  int xi0=(int)x0, xi1=(int)x1, yi0=(int)y0, yi1=(int)y1;
  const float* xb = x + b*65536;
  float Ia = xb[yi0*256+xi0], Ib = xb[yi1*256+xi0];
  float Ic = xb[yi0*256+xi1], Id = xb[yi1*256+xi1];
  float r0 = wa*Ia + wb*Ib + wc*Ic + wd*Id;
  const float4* pa = (const float4*)&g_xi[((b*32 + (yi0>>3))*32 + (xi0>>3))*32];
  const float4* pb = (const float4*)&g_xi[((b*32 + (yi1>>3))*32 + (xi0>>3))*32];
  const float4* pc = (const float4*)&g_xi[((b*32 + (yi0>>3))*32 + (xi1>>3))*32];
  const float4* pd = (const float4*)&g_xi[((b*32 + (yi1>>3))*32 + (xi1>>3))*32];
  float4* ob = (float4*)(out + ((size_t)blockIdx.x*256 + px)*32);
  #pragma unroll
  for (int j=0;j<8;j++){
    float4 va = pa[j], vb = pb[j], vc = pc[j], vd = pd[j];
    float4 r;
    r.x = wa*va.x + wb*vb.x + wc*vc.x + wd*vd.x;
    r.y = wa*va.y + wb*vb.y + wc*vc.y + wd*vd.y;
    r.z = wa*va.z + wb*vb.z + wc*vc.z + wd*vd.z;
    r.w = wa*va.w + wb*vb.w + wc*vc.w + wd*vd.w;
    if (j == 0) r.x = r0;                       // channel 0 = raw image sample
    r.x = (r.x >= 0.f) ? r.x : 0.1f*r.x;
    r.y = (r.y >= 0.f) ? r.y : 0.1f*r.y;
    r.z = (r.z >= 0.f) ? r.z : 0.1f*r.z;
    r.w = (r.w >= 0.f) ? r.w : 0.1f*r.w;
    ob[j] = r;
  }
}

// ================= launch =================
extern "C" void kernel_launch(void* const* d_in, const int* in_sizes, int n_in,
                              void* d_out, int out_size){
  const float* x     = (const float*)d_in[0];
  const float* c1k   = (const float*)d_in[1];
  const float* c1b   = (const float*)d_in[2];
  const float* c2k   = (const float*)d_in[3];
  const float* c2b   = (const float*)d_in[4];
  const float* c3k   = (const float*)d_in[5];
  const float* c3b   = (const float*)d_in[6];
  const float* gamma = (const float*)d_in[7];
  const float* beta  = (const float*)d_in[8];
  const float* mean  = (const float*)d_in[9];
  const float* var   = (const float*)d_in[10];
  const float* d1k   = (const float*)d_in[11];
  const float* d1b   = (const float*)d_in[12];
  const float* d2k   = (const float*)d_in[13];
  const float* d2b   = (const float*)d_in[14];
  const float* d3k   = (const float*)d_in[15];
  const float* d3b   = (const float*)d_in[16];
  float* out = (float*)d_out;

  k_conv1<<<1024, 256>>>(x, c1k, c1b);
  k_conv2<<<1024, 256>>>(c2k, c2b);
  k_conv3<<<512, 256>>>(c3k, c3b);
  k_d1<<<dim3(31,16), 256>>>(gamma, beta, mean, var, d1k);
  k_d23<<<16, 96>>>(d1b, d2k, d2b, d3k, d3b);
  k_sample<<<4096, 256>>>(x, out);
}

// round 5
// speedup vs baseline: 1.4223x; 1.4223x over previous
#include <cuda_runtime.h>

#define BN_EPS 1e-3f
typedef unsigned long long ull;

// ---------------- scratch (device globals, no allocation) ----------------
// conv1 out, parity-split: [b][y(128)][parity(2)][xh(64)][8c]   (8 MB)
__device__ __align__(16) float g_a1[16*128*2*64*8];
// conv2 out, parity+cgroup split: [b][y(64)][cg(4)][parity(2)][xh(32)][4c]  (4 MB)
__device__ __align__(16) float g_a2[16*64*4*2*32*4];
// conv3 out, sampler layout: [b][y(32)][x(32)][32c] (slot0 = 0 pad, ch c at c+1)  (2 MB)
__device__ __align__(16) float g_xi[16*32*32*32];
__device__ float g_f1[16*64];
__device__ float g_theta[16*6];
__device__ unsigned g_ctr;

#define FMA4(A, s, W) { A.x += (s)*(W).x; A.y += (s)*(W).y; A.z += (s)*(W).z; A.w += (s)*(W).w; }

__device__ __forceinline__ ull pack2(float lo, float hi){
  ull r; asm("mov.b64 %0, {%1,%2};" : "=l"(r) : "f"(lo), "f"(hi)); return r;
}
__device__ __forceinline__ void fma2(ull& acc, ull a, ull b){
  asm("fma.rn.f32x2 %0, %1, %2, %0;" : "+l"(acc) : "l"(a), "l"(b));
}
__device__ __forceinline__ float2 unpack2(ull v){
  float2 r; asm("mov.b64 {%0,%1}, %2;" : "=f"(r.x), "=f"(r.y) : "l"(v)); return r;
}

// ================= conv1 (1->8) + relu + maxpool2 =================
__global__ void __launch_bounds__(256) k_conv1(const float* __restrict__ x,
                        const float* __restrict__ w,
                        const float* __restrict__ bias){
  __shared__ float sw[72];
  __shared__ float sb[8];
  int t = threadIdx.x;
  if (t < 72) sw[t] = w[t];
  if (t < 8)  sb[t] = bias[t];
  __syncthreads();
  int id = blockIdx.x*256 + t;                 // 16*128*128 threads
  int px = id & 127, py = (id>>7)&127, bb = id>>14;
  const float* xb = x + bb*65536;
  float in[4][4];
  #pragma unroll
  for (int dy=0; dy<4; dy++){
    int iy = 2*py + dy - 1;
    #pragma unroll
    for (int dx=0; dx<4; dx++){
      int ix = 2*px + dx - 1;
      in[dy][dx] = (iy>=0 && iy<256 && ix>=0 && ix<256) ? xb[iy*256+ix] : 0.f;
    }
  }
  float acc[2][2][8];
  #pragma unroll
  for (int p=0;p<2;p++)
    #pragma unroll
    for (int q=0;q<2;q++)
      #pragma unroll
      for (int oc=0;oc<8;oc++) acc[p][q][oc]=0.f;
  #pragma unroll
  for (int ky=0;ky<3;ky++){
    #pragma unroll
    for (int kx=0;kx<3;kx++){
      float wv[8];
      #pragma unroll
      for (int oc=0;oc<8;oc++) wv[oc] = sw[(ky*3+kx)*8+oc];
      #pragma unroll
      for (int p=0;p<2;p++){
        #pragma unroll
        for (int q=0;q<2;q++){
          float v = in[p+ky][q+kx];
          #pragma unroll
          for (int oc=0;oc<8;oc++) acc[p][q][oc] += v*wv[oc];
        }
      }
    }
  }
  float o[8];
  #pragma unroll
  for (int oc=0;oc<8;oc++){
    float m = fmaxf(fmaxf(acc[0][0][oc],acc[0][1][oc]),
                    fmaxf(acc[1][0][oc],acc[1][1][oc]));
    o[oc] = fmaxf(m + sb[oc], 0.f);
  }
  int par = px & 1, xh = px >> 1;
  float4* dst = (float4*)&g_a1[(size_t)((((bb*128+py)*2+par)*64+xh))*8];
  dst[0] = make_float4(o[0],o[1],o[2],o[3]);
  dst[1] = make_float4(o[4],o[5],o[6],o[7]);
}

// ================= conv2 (8->16) + relu + maxpool2 =================
// parity-split input reads: lane-contiguous.  f32x2 packed FMAs.
__global__ void __launch_bounds__(256) k_conv2(const float* __restrict__ w, const float* __restrict__ bias){
  __shared__ __align__(16) float sw[1152];     // [tap][ic(8)][oc(16)]
  __shared__ float sb[16];
  int t = threadIdx.x;
  for (int i=t; i<1152; i+=256) sw[i] = w[i];
  if (t < 16) sb[t] = bias[t];
  __syncthreads();
  int id = blockIdx.x*256 + t;                 // 4*16*64*64 = 262144 threads
  int px = id & 63, py = (id>>6)&63, bb = (id>>12)&15, ch = id>>16;
  ull acc[4][2];
  #pragma unroll
  for (int i=0;i<4;i++){ acc[i][0]=0ull; acc[i][1]=0ull; }
  #pragma unroll
  for (int ky=0; ky<3; ky++){
    #pragma unroll
    for (int kx=0; kx<3; kx++){
      float4 pv[2][2][2];                      // [p][q][half]
      #pragma unroll
      for (int p=0;p<2;p++){
        #pragma unroll
        for (int q=0;q<2;q++){
          int e = p + ky - 1, d = q + kx - 1;
          int iy = 2*py + e;
          int par = d & 1, xh = px + (d >> 1);
          float4 lo = make_float4(0,0,0,0), hi = lo;
          if (iy>=0 && iy<128 && xh>=0 && xh<64){
            const float4* pp = (const float4*)&g_a1[(size_t)((((bb*128+iy)*2+par)*64+xh))*8];
            lo = pp[0]; hi = pp[1];
          }
          pv[p][q][0] = lo; pv[p][q][1] = hi;
        }
      }
      #pragma unroll
      for (int hf=0; hf<2; hf++){
        #pragma unroll
        for (int l=0; l<4; l++){
          int ic = hf*4 + l;
          const ull* wp = (const ull*)&sw[((ky*3+kx)*8 + ic)*16 + ch*4];
          ull w01 = wp[0], w23 = wp[1];
          #pragma unroll
          for (int p=0;p<2;p++){
            #pragma unroll
            for (int q=0;q<2;q++){
              float s = ((const float*)&pv[p][q][hf])[l];
              ull s2 = pack2(s, s);
              fma2(acc[p*2+q][0], s2, w01);
              fma2(acc[p*2+q][1], s2, w23);
            }
          }
        }
      }
    }
  }
  float o[4];
  #pragma unroll
  for (int j=0;j<2;j++){
    float2 a = unpack2(acc[0][j]), b2 = unpack2(acc[1][j]);
    float2 c = unpack2(acc[2][j]), d2 = unpack2(acc[3][j]);
    o[j*2+0] = fmaxf(fmaxf(a.x,b2.x),fmaxf(c.x,d2.x));
    o[j*2+1] = fmaxf(fmaxf(a.y,b2.y),fmaxf(c.y,d2.y));
  }
  float4 m;
  m.x = fmaxf(o[0] + sb[ch*4+0], 0.f);
  m.y = fmaxf(o[1] + sb[ch*4+1], 0.f);
  m.z = fmaxf(o[2] + sb[ch*4+2], 0.f);
  m.w = fmaxf(o[3] + sb[ch*4+3], 0.f);
  int par = px & 1, xh = px >> 1;
  *(float4*)&g_a2[(size_t)(((((bb*64+py)*4+ch)*2+par)*32+xh))*4] = m;
}

// ================= conv3 (16->31) + relu + maxpool2 =================
__global__ void __launch_bounds__(256) k_conv3(const float* __restrict__ w, const float* __restrict__ bias){
  __shared__ __align__(16) float sw[4608];     // [tap][ic(16)][ocpad(32)]
  __shared__ float sb[32];
  int t = threadIdx.x;
  for (int i=t; i<4608; i+=256){
    int tap_ic = i >> 5, oc = i & 31;
    sw[i] = (oc < 31) ? w[tap_ic*31 + oc] : 0.f;
  }
  if (t < 32) sb[t] = (t < 31) ? bias[t] : 0.f;
  if (blockIdx.x == 0){                         // zero d1 accumulators + counter
    for (int i=t; i<1024; i+=256) g_f1[i] = 0.f;
    if (t == 0) g_ctr = 0u;
  }
  __syncthreads();
  int id = blockIdx.x*256 + t;                  // 8*16*32*32 = 131072 threads
  int px = id & 31, py = (id>>5)&31, bb = (id>>10)&15, ch = id>>14;
  ull acc[4][2];
  #pragma unroll
  for (int i=0;i<4;i++){ acc[i][0]=0ull; acc[i][1]=0ull; }
  #pragma unroll
  for (int ky=0; ky<3; ky++){
    #pragma unroll
    for (int kx=0; kx<3; kx++){
      #pragma unroll
      for (int cg=0; cg<4; cg++){
        float4 pv[2][2];
        #pragma unroll
        for (int p=0;p<2;p++){
          #pragma unroll
          for (int q=0;q<2;q++){
            int e = p + ky - 1, d = q + kx - 1;
            int iy = 2*py + e;
            int par = d & 1, xh = px + (d >> 1);
            float4 v = make_float4(0,0,0,0);
            if (iy>=0 && iy<64 && xh>=0 && xh<32){
              v = *(const float4*)&g_a2[(size_t)(((((bb*64+iy)*4+cg)*2+par)*32+xh))*4];
            }
            pv[p][q] = v;
          }
        }
        #pragma unroll
        for (int l=0; l<4; l++){
          int ic = cg*4 + l;
          const ull* wp = (const ull*)&sw[((ky*3+kx)*16 + ic)*32 + ch*4];
          ull w01 = wp[0], w23 = wp[1];
          #pragma unroll
          for (int p=0;p<2;p++){
            #pragma unroll
            for (int q=0;q<2;q++){
              float s = ((const float*)&pv[p][q])[l];
              ull s2 = pack2(s, s);
              fma2(acc[p*2+q][0], s2, w01);
              fma2(acc[p*2+q][1], s2, w23);
            }
          }
        }
      }
    }
  }
  float mv[4];
  #pragma unroll
  for (int j=0;j<2;j++){
    float2 a = unpack2(acc[0][j]), b2 = unpack2(acc[1][j]);
    float2 c = unpack2(acc[2][j]), d2 = unpack2(acc[3][j]);
    mv[j*2+0] = fmaxf(fmaxf(fmaxf(a.x,b2.x),fmaxf(c.x,d2.x)) + sb[ch*4+j*2+0], 0.f);
    mv[j*2+1] = fmaxf(fmaxf(fmaxf(a.y,b2.y),fmaxf(c.y,d2.y)) + sb[ch*4+j*2+1], 0.f);
  }
  int pixbase = ((bb*32+py)*32+px)*32;
  if (ch == 0) g_xi[pixbase] = 0.f;             // channel-0 pad slot
  #pragma unroll
  for (int j=0;j<4;j++){
    int oc = ch*4 + j;
    if (oc < 31) g_xi[pixbase + 1 + oc] = mv[j];
  }
}

// ======= BN-fold + dense1 (31744->64) split-K, batch-shared; d2/d3 in tail block =======
__global__ void __launch_bounds__(256) k_d1(
      const float* __restrict__ gamma, const float* __restrict__ beta,
      const float* __restrict__ mean,  const float* __restrict__ var,
      const float* __restrict__ d1k,   const float* __restrict__ d1b,
      const float* __restrict__ d2k,   const float* __restrict__ d2b,
      const float* __restrict__ d3k,   const float* __restrict__ d3b){
  __shared__ float sc[128], sh[128];
  __shared__ float sf[16][128];
  __shared__ float s1[16][64];
  __shared__ float s2[16][96];
  __shared__ unsigned slast;
  int t  = threadIdx.x;
  int cb = blockIdx.x * 128;                    // 248 blocks
  if (t < 128){
    int i = cb + t;
    float scale = gamma[i] * rsqrtf(var[i] + BN_EPS);
    sc[t] = scale;
    sh[t] = beta[i] - mean[i]*scale;
  }
  __syncthreads();
  for (int idx=t; idx<2048; idx+=256){
    int b = idx >> 7, f = idx & 127;
    int i = cb + f;
    int c = i % 31;
    int rest = i / 31;                          // = y*32 + x
    sf[b][f] = g_xi[(b*1024 + rest)*32 + 1 + c] * sc[f] + sh[f];
  }
  __syncthreads();
  {
    int b = t >> 4, c4 = t & 15;
    const float4* k4 = (const float4*)d1k;
    float4 acc = make_float4(0,0,0,0);
    #pragma unroll 4
    for (int f=0; f<128; f++){
      float s = sf[b][f];
      float4 wv = k4[(size_t)(cb+f)*16 + c4];
      FMA4(acc, s, wv);
    }
    atomicAdd(&g_f1[b*64 + c4*4 + 0], acc.x);
    atomicAdd(&g_f1[b*64 + c4*4 + 1], acc.y);
    atomicAdd(&g_f1[b*64 + c4*4 + 2], acc.z);
    atomicAdd(&g_f1[b*64 + c4*4 + 3], acc.w);
  }
  __threadfence();
  if (t == 0) slast = atomicAdd(&g_ctr, 1u);
  __syncthreads();
  if (slast != gridDim.x - 1) return;
  // ---- tail block: d1 bias+relu, d2, d3 ----
  for (int i=t; i<1024; i+=256){
    int b = i >> 6, j = i & 63;
    float v = ((volatile float*)g_f1)[i];
    s1[b][j] = fmaxf(v + d1b[j], 0.f);
  }
  __syncthreads();
  for (int o=t; o<1536; o+=256){
    int b = o / 96, j = o % 96;
    float a = d2b[j];
    #pragma unroll 8
    for (int k=0; k<64; k++) a += s1[b][k]*d2k[k*96+j];
    s2[b][j] = fmaxf(a, 0.f);
  }
  __syncthreads();
  if (t < 96){
    int b = t / 6, j = t % 6;
    float a = d3b[j];
    #pragma unroll 8
    for (int k=0; k<96; k++) a += s2[b][k]*d3k[k*6+j];
    g_theta[t] = a;
  }
}

// ================= grid-gen + bilinear sampler + leaky relu =================
__global__ void __launch_bounds__(256) k_sample(const float* __restrict__ x, float* __restrict__ out){
  __shared__ float th[6];
  int b = blockIdx.x >> 8;
  int y = blockIdx.x & 255;
  int px = threadIdx.x;
  if (px < 6) th[px] = g_theta[b*6+px];
  __syncthreads();
  float gxn = ((float)px / 255.f)*2.f - 1.f;
  float gyn = ((float)y  / 255.f)*2.f - 1.f;
  float tgx = gxn*th[0] + gyn*th[3] + th[2];
  float tgy = gxn*th[1] + gyn*th[4] + th[5];
  float fx = 0.5f*((tgx + 1.f)*255.f);
  float fy = 0.5f*((tgy + 1.f)*255.f);
  float x0 = floorf(fx), x1 = x0 + 1.f;
  float y0 = floorf(fy), y1 = y0 + 1.f;
  x0 = fminf(fmaxf(x0,0.f),255.f);  x1 = fminf(fmaxf(x1,0.f),255.f);
  y0 = fminf(fmaxf(y0,0.f),255.f);  y1 = fminf(fmaxf(y1,0.f),255.f);
  float wa = (x1-fx)*(y1-fy);
  float wb = (x1-fx)*(fy-y0);
  float wc = (fx-x0)*(y1-fy);
  float wd = (fx-x0)*(fy-y0);
  int xi0=(int)x0, xi1=(int)x1, yi0=(int)y0, yi1=(int)y1;
  const float* xb = x + b*65536;
  float Ia = xb[yi0*256+xi0], Ib = xb[yi1*256+xi0];
  float Ic = xb[yi0*256+xi1], Id = xb[yi1*256+xi1];
  float r0 = wa*Ia + wb*Ib + wc*Ic + wd*Id;
  const float4* pa = (const float4*)&g_xi[((b*32 + (yi0>>3))*32 + (xi0>>3))*32];
  const float4* pb = (const float4*)&g_xi[((b*32 + (yi1>>3))*32 + (xi0>>3))*32];
  const float4* pc = (const float4*)&g_xi[((b*32 + (yi0>>3))*32 + (xi1>>3))*32];
  const float4* pd = (const float4*)&g_xi[((b*32 + (yi1>>3))*32 + (xi1>>3))*32];
  float4* ob = (float4*)(out + ((size_t)blockIdx.x*256 + px)*32);
  #pragma unroll
  for (int j=0;j<8;j++){
    float4 va = pa[j], vb = pb[j], vc = pc[j], vd = pd[j];
    float4 r;
    r.x = wa*va.x + wb*vb.x + wc*vc.x + wd*vd.x;
    r.y = wa*va.y + wb*vb.y + wc*vc.y + wd*vd.y;
    r.z = wa*va.z + wb*vb.z + wc*vc.z + wd*vd.z;
    r.w = wa*va.w + wb*vb.w + wc*vc.w + wd*vd.w;
    if (j == 0) r.x = r0;                       // channel 0 = raw image sample
    r.x = (r.x >= 0.f) ? r.x : 0.1f*r.x;
    r.y = (r.y >= 0.f) ? r.y : 0.1f*r.y;
    r.z = (r.z >= 0.f) ? r.z : 0.1f*r.z;
    r.w = (r.w >= 0.f) ? r.w : 0.1f*r.w;
    ob[j] = r;
  }
}

// ================= launch =================
extern "C" void kernel_launch(void* const* d_in, const int* in_sizes, int n_in,
                              void* d_out, int out_size){
  const float* x     = (const float*)d_in[0];
  const float* c1k   = (const float*)d_in[1];
  const float* c1b   = (const float*)d_in[2];
  const float* c2k   = (const float*)d_in[3];
  const float* c2b   = (const float*)d_in[4];
  const float* c3k   = (const float*)d_in[5];
  const float* c3b   = (const float*)d_in[6];
  const float* gamma = (const float*)d_in[7];
  const float* beta  = (const float*)d_in[8];
  const float* mean  = (const float*)d_in[9];
  const float* var   = (const float*)d_in[10];
  const float* d1k   = (const float*)d_in[11];
  const float* d1b   = (const float*)d_in[12];
  const float* d2k   = (const float*)d_in[13];
  const float* d2b   = (const float*)d_in[14];
  const float* d3k   = (const float*)d_in[15];
  const float* d3b   = (const float*)d_in[16];
  float* out = (float*)d_out;

  k_conv1<<<1024, 256>>>(x, c1k, c1b);
  k_conv2<<<1024, 256>>>(c2k, c2b);
  k_conv3<<<512, 256>>>(c3k, c3b);
  k_d1<<<248, 256>>>(gamma, beta, mean, var, d1k, d1b, d2k, d2b, d3k, d3b);
  k_sample<<<4096, 256>>>(x, out);
}

// round 6
// speedup vs baseline: 1.7149x; 1.2058x over previous
#include <cuda_runtime.h>

#define BN_EPS 1e-3f
typedef unsigned long long ull;

// ---------------- scratch (device globals, no allocation) ----------------
// conv1 out, parity-split: [b][y(128)][parity(2)][xh(64)][8c]   (8 MB)
__device__ __align__(16) float g_a1[16*128*2*64*8];
// conv2 out, parity+cgroup split: [b][y(64)][cg(4)][parity(2)][xh(32)][4c]  (4 MB)
__device__ __align__(16) float g_a2[16*64*4*2*32*4];
// conv3 out, sampler layout: [b][y(32)][x(32)][32c] (slot0 = 0 pad, ch c at c+1)  (2 MB)
__device__ __align__(16) float g_xi[16*32*32*32];
__device__ float g_f1[16*64];
__device__ float g_theta[16*6];
__device__ unsigned g_ctr;

#define FMA4(A, s, W) { A.x += (s)*(W).x; A.y += (s)*(W).y; A.z += (s)*(W).z; A.w += (s)*(W).w; }

__device__ __forceinline__ ull pack2(float lo, float hi){
  ull r; asm("mov.b64 %0, {%1,%2};" : "=l"(r) : "f"(lo), "f"(hi)); return r;
}
__device__ __forceinline__ void fma2(ull& acc, ull a, ull b){
  asm("fma.rn.f32x2 %0, %1, %2, %0;" : "+l"(acc) : "l"(a), "l"(b));
}
__device__ __forceinline__ float2 unpack2(ull v){
  float2 r; asm("mov.b64 {%0,%1}, %2;" : "=f"(r.x), "=f"(r.y) : "l"(v)); return r;
}

// ================= conv1 (1->8) + relu + maxpool2 =================
__global__ void __launch_bounds__(256) k_conv1(const float* __restrict__ x,
                        const float* __restrict__ w,
                        const float* __restrict__ bias){
  __shared__ float sw[72];
  __shared__ float sb[8];
  int t = threadIdx.x;
  if (t < 72) sw[t] = w[t];
  if (t < 8)  sb[t] = bias[t];
  __syncthreads();
  int id = blockIdx.x*256 + t;                 // 16*128*128 threads
  int px = id & 127, py = (id>>7)&127, bb = id>>14;
  const float* xb = x + bb*65536;
  float in[4][4];
  #pragma unroll
  for (int dy=0; dy<4; dy++){
    int iy = 2*py + dy - 1;
    #pragma unroll
    for (int dx=0; dx<4; dx++){
      int ix = 2*px + dx - 1;
      in[dy][dx] = (iy>=0 && iy<256 && ix>=0 && ix<256) ? xb[iy*256+ix] : 0.f;
    }
  }
  float acc[2][2][8];
  #pragma unroll
  for (int p=0;p<2;p++)
    #pragma unroll
    for (int q=0;q<2;q++)
      #pragma unroll
      for (int oc=0;oc<8;oc++) acc[p][q][oc]=0.f;
  #pragma unroll
  for (int ky=0;ky<3;ky++){
    #pragma unroll
    for (int kx=0;kx<3;kx++){
      float wv[8];
      #pragma unroll
      for (int oc=0;oc<8;oc++) wv[oc] = sw[(ky*3+kx)*8+oc];
      #pragma unroll
      for (int p=0;p<2;p++){
        #pragma unroll
        for (int q=0;q<2;q++){
          float v = in[p+ky][q+kx];
          #pragma unroll
          for (int oc=0;oc<8;oc++) acc[p][q][oc] += v*wv[oc];
        }
      }
    }
  }
  float o[8];
  #pragma unroll
  for (int oc=0;oc<8;oc++){
    float m = fmaxf(fmaxf(acc[0][0][oc],acc[0][1][oc]),
                    fmaxf(acc[1][0][oc],acc[1][1][oc]));
    o[oc] = fmaxf(m + sb[oc], 0.f);
  }
  int par = px & 1, xh = px >> 1;
  float4* dst = (float4*)&g_a1[(size_t)((((bb*128+py)*2+par)*64+xh))*8];
  dst[0] = make_float4(o[0],o[1],o[2],o[3]);
  dst[1] = make_float4(o[4],o[5],o[6],o[7]);
}

// ================= conv2 (8->16) + relu + maxpool2 =================
__global__ void __launch_bounds__(256) k_conv2(const float* __restrict__ w, const float* __restrict__ bias){
  __shared__ __align__(16) float sw[1152];     // [tap][ic(8)][oc(16)]
  __shared__ float sb[16];
  int t = threadIdx.x;
  for (int i=t; i<1152; i+=256) sw[i] = w[i];
  if (t < 16) sb[t] = bias[t];
  __syncthreads();
  int id = blockIdx.x*256 + t;                 // 4*16*64*64 = 262144 threads
  int px = id & 63, py = (id>>6)&63, bb = (id>>12)&15, ch = id>>16;
  ull acc[4][2];
  #pragma unroll
  for (int i=0;i<4;i++){ acc[i][0]=0ull; acc[i][1]=0ull; }
  #pragma unroll
  for (int ky=0; ky<3; ky++){
    #pragma unroll
    for (int kx=0; kx<3; kx++){
      float4 pv[2][2][2];                      // [p][q][half]
      #pragma unroll
      for (int p=0;p<2;p++){
        #pragma unroll
        for (int q=0;q<2;q++){
          int e = p + ky - 1, d = q + kx - 1;
          int iy = 2*py + e;
          int par = d & 1, xh = px + (d >> 1);
          float4 lo = make_float4(0,0,0,0), hi = lo;
          if (iy>=0 && iy<128 && xh>=0 && xh<64){
            const float4* pp = (const float4*)&g_a1[(size_t)((((bb*128+iy)*2+par)*64+xh))*8];
            lo = pp[0]; hi = pp[1];
          }
          pv[p][q][0] = lo; pv[p][q][1] = hi;
        }
      }
      #pragma unroll
      for (int hf=0; hf<2; hf++){
        #pragma unroll
        for (int l=0; l<4; l++){
          int ic = hf*4 + l;
          const ull* wp = (const ull*)&sw[((ky*3+kx)*8 + ic)*16 + ch*4];
          ull w01 = wp[0], w23 = wp[1];
          #pragma unroll
          for (int p=0;p<2;p++){
            #pragma unroll
            for (int q=0;q<2;q++){
              float s = ((const float*)&pv[p][q][hf])[l];
              ull s2 = pack2(s, s);
              fma2(acc[p*2+q][0], s2, w01);
              fma2(acc[p*2+q][1], s2, w23);
            }
          }
        }
      }
    }
  }
  float o[4];
  #pragma unroll
  for (int j=0;j<2;j++){
    float2 a = unpack2(acc[0][j]), b2 = unpack2(acc[1][j]);
    float2 c = unpack2(acc[2][j]), d2 = unpack2(acc[3][j]);
    o[j*2+0] = fmaxf(fmaxf(a.x,b2.x),fmaxf(c.x,d2.x));
    o[j*2+1] = fmaxf(fmaxf(a.y,b2.y),fmaxf(c.y,d2.y));
  }
  float4 m;
  m.x = fmaxf(o[0] + sb[ch*4+0], 0.f);
  m.y = fmaxf(o[1] + sb[ch*4+1], 0.f);
  m.z = fmaxf(o[2] + sb[ch*4+2], 0.f);
  m.w = fmaxf(o[3] + sb[ch*4+3], 0.f);
  int par = px & 1, xh = px >> 1;
  *(float4*)&g_a2[(size_t)(((((bb*64+py)*4+ch)*2+par)*32+xh))*4] = m;
}

// ================= conv3 (16->31) + relu + maxpool2 =================
__global__ void __launch_bounds__(256) k_conv3(const float* __restrict__ w, const float* __restrict__ bias){
  __shared__ __align__(16) float sw[4608];     // [tap][ic(16)][ocpad(32)]
  __shared__ float sb[32];
  int t = threadIdx.x;
  for (int i=t; i<4608; i+=256){
    int tap_ic = i >> 5, oc = i & 31;
    sw[i] = (oc < 31) ? w[tap_ic*31 + oc] : 0.f;
  }
  if (t < 32) sb[t] = (t < 31) ? bias[t] : 0.f;
  if (blockIdx.x == 0){                         // zero d1 accumulators + counter
    for (int i=t; i<1024; i+=256) g_f1[i] = 0.f;
    if (t == 0) g_ctr = 0u;
  }
  __syncthreads();
  int id = blockIdx.x*256 + t;                  // 8*16*32*32 = 131072 threads
  int px = id & 31, py = (id>>5)&31, bb = (id>>10)&15, ch = id>>14;
  ull acc[4][2];
  #pragma unroll
  for (int i=0;i<4;i++){ acc[i][0]=0ull; acc[i][1]=0ull; }
  #pragma unroll
  for (int ky=0; ky<3; ky++){
    #pragma unroll
    for (int kx=0; kx<3; kx++){
      #pragma unroll
      for (int cg=0; cg<4; cg++){
        float4 pv[2][2];
        #pragma unroll
        for (int p=0;p<2;p++){
          #pragma unroll
          for (int q=0;q<2;q++){
            int e = p + ky - 1, d = q + kx - 1;
            int iy = 2*py + e;
            int par = d & 1, xh = px + (d >> 1);
            float4 v = make_float4(0,0,0,0);
            if (iy>=0 && iy<64 && xh>=0 && xh<32){
              v = *(const float4*)&g_a2[(size_t)(((((bb*64+iy)*4+cg)*2+par)*32+xh))*4];
            }
            pv[p][q] = v;
          }
        }
        #pragma unroll
        for (int l=0; l<4; l++){
          int ic = cg*4 + l;
          const ull* wp = (const ull*)&sw[((ky*3+kx)*16 + ic)*32 + ch*4];
          ull w01 = wp[0], w23 = wp[1];
          #pragma unroll
          for (int p=0;p<2;p++){
            #pragma unroll
            for (int q=0;q<2;q++){
              float s = ((const float*)&pv[p][q])[l];
              ull s2 = pack2(s, s);
              fma2(acc[p*2+q][0], s2, w01);
              fma2(acc[p*2+q][1], s2, w23);
            }
          }
        }
      }
    }
  }
  float mv[4];
  #pragma unroll
  for (int j=0;j<2;j++){
    float2 a = unpack2(acc[0][j]), b2 = unpack2(acc[1][j]);
    float2 c = unpack2(acc[2][j]), d2 = unpack2(acc[3][j]);
    mv[j*2+0] = fmaxf(fmaxf(fmaxf(a.x,b2.x),fmaxf(c.x,d2.x)) + sb[ch*4+j*2+0], 0.f);
    mv[j*2+1] = fmaxf(fmaxf(fmaxf(a.y,b2.y),fmaxf(c.y,d2.y)) + sb[ch*4+j*2+1], 0.f);
  }
  int pixbase = ((bb*32+py)*32+px)*32;
  if (ch == 0) g_xi[pixbase] = 0.f;             // channel-0 pad slot
  #pragma unroll
  for (int j=0;j<4;j++){
    int oc = ch*4 + j;
    if (oc < 31) g_xi[pixbase + 1 + oc] = mv[j];
  }
}

// ======= BN-fold + dense1 (31744->64): 124 K-chunks x 4 batch-groups =======
// Each block: 256 f-rows, 4 batches. Thread (fg,c4) owns a 16-row slice and
// 4 batch accumulators -> 16 independent LDG.128 + 16 indep FMA4 per load.
__global__ void __launch_bounds__(256) k_d1(
      const float* __restrict__ gamma, const float* __restrict__ beta,
      const float* __restrict__ mean,  const float* __restrict__ var,
      const float* __restrict__ d1k,   const float* __restrict__ d1b,
      const float* __restrict__ d2k,   const float* __restrict__ d2b,
      const float* __restrict__ d3k,   const float* __restrict__ d3b){
  __shared__ float sc[256], sh[256];
  __shared__ float sf[4][256];
  __shared__ float sred[4][16][64];
  __shared__ float s1[16][64];
  __shared__ float s2[16][96];
  __shared__ unsigned slast;
  int t  = threadIdx.x;
  int kc = blockIdx.x >> 2;                     // 0..123
  int bg = blockIdx.x & 3;                      // 0..3  (batches bg*4 .. bg*4+3)
  int cb = kc * 256;
  {
    int i = cb + t;
    float scale = gamma[i] * rsqrtf(var[i] + BN_EPS);
    sc[t] = scale;
    sh[t] = beta[i] - mean[i]*scale;
  }
  __syncthreads();
  for (int idx=t; idx<1024; idx+=256){
    int bl = idx >> 8, f = idx & 255;
    int i = cb + f;
    int c = i % 31;
    int rest = i / 31;                          // = y*32 + x
    sf[bl][f] = g_xi[((bg*4+bl)*1024 + rest)*32 + 1 + c] * sc[f] + sh[f];
  }
  __syncthreads();
  int c4 = t & 15;                              // column group (4 cols)
  int fg = t >> 4;                              // 16 f-groups of 16 rows
  float4 a0 = make_float4(0,0,0,0), a1 = a0, a2 = a0, a3 = a0;
  {
    const float4* k4 = (const float4*)d1k + (size_t)(cb + fg*16)*16 + c4;
    const float* sfp = &sf[0][fg*16];
    #pragma unroll
    for (int j=0; j<16; j++){
      float4 wv = k4[j*16];
      float s0 = sfp[j], s1v = sfp[256+j], s2v = sfp[512+j], s3v = sfp[768+j];
      FMA4(a0, s0, wv);
      FMA4(a1, s1v, wv);
      FMA4(a2, s2v, wv);
      FMA4(a3, s3v, wv);
    }
  }
  *(float4*)&sred[0][fg][c4*4] = a0;
  *(float4*)&sred[1][fg][c4*4] = a1;
  *(float4*)&sred[2][fg][c4*4] = a2;
  *(float4*)&sred[3][fg][c4*4] = a3;
  __syncthreads();
  {
    int bl = t >> 6, col = t & 63;
    float s = 0.f;
    #pragma unroll
    for (int g=0; g<16; g++) s += sred[bl][g][col];
    atomicAdd(&g_f1[(bg*4+bl)*64 + col], s);
  }
  __threadfence();
  if (t == 0) slast = atomicAdd(&g_ctr, 1u);
  __syncthreads();
  if (slast != gridDim.x - 1) return;
  // ---- tail block: d1 bias+relu, d2, d3 ----
  for (int i=t; i<1024; i+=256){
    int b = i >> 6, j = i & 63;
    float v = ((volatile float*)g_f1)[i];
    s1[b][j] = fmaxf(v + d1b[j], 0.f);
  }
  __syncthreads();
  for (int o=t; o<1536; o+=256){
    int b = o / 96, j = o % 96;
    float a = d2b[j];
    #pragma unroll 8
    for (int k=0; k<64; k++) a += s1[b][k]*d2k[k*96+j];
    s2[b][j] = fmaxf(a, 0.f);
  }
  __syncthreads();
  if (t < 96){
    int b = t / 6, j = t % 6;
    float a = d3b[j];
    #pragma unroll 8
    for (int k=0; k<96; k++) a += s2[b][k]*d3k[k*6+j];
    g_theta[t] = a;
  }
}

// ================= grid-gen + bilinear sampler + leaky relu =================
__global__ void __launch_bounds__(256) k_sample(const float* __restrict__ x, float* __restrict__ out){
  __shared__ float th[6];
  int b = blockIdx.x >> 8;
  int y = blockIdx.x & 255;
  int px = threadIdx.x;
  if (px < 6) th[px] = g_theta[b*6+px];
  __syncthreads();
  float gxn = ((float)px / 255.f)*2.f - 1.f;
  float gyn = ((float)y  / 255.f)*2.f - 1.f;
  float tgx = gxn*th[0] + gyn*th[3] + th[2];
  float tgy = gxn*th[1] + gyn*th[4] + th[5];
  float fx = 0.5f*((tgx + 1.f)*255.f);
  float fy = 0.5f*((tgy + 1.f)*255.f);
  float x0 = floorf(fx), x1 = x0 + 1.f;
  float y0 = floorf(fy), y1 = y0 + 1.f;
  x0 = fminf(fmaxf(x0,0.f),255.f);  x1 = fminf(fmaxf(x1,0.f),255.f);
  y0 = fminf(fmaxf(y0,0.f),255.f);  y1 = fminf(fmaxf(y1,0.f),255.f);
  float wa = (x1-fx)*(y1-fy);
  float wb = (x1-fx)*(fy-y0);
  float wc = (fx-x0)*(y1-fy);
  float wd = (fx-x0)*(fy-y0);
  int xi0=(int)x0, xi1=(int)x1, yi0=(int)y0, yi1=(int)y1;
  const float* xb = x + b*65536;
  float Ia = xb[yi0*256+xi0], Ib = xb[yi1*256+xi0];
  float Ic = xb[yi0*256+xi1], Id = xb[yi1*256+xi1];
  float r0 = wa*Ia + wb*Ib + wc*Ic + wd*Id;
  const float4* pa = (const float4*)&g_xi[((b*32 + (yi0>>3))*32 + (xi0>>3))*32];
  const float4* pb = (const float4*)&g_xi[((b*32 + (yi1>>3))*32 + (xi0>>3))*32];
  const float4* pc = (const float4*)&g_xi[((b*32 + (yi0>>3))*32 + (xi1>>3))*32];
  const float4* pd = (const float4*)&g_xi[((b*32 + (yi1>>3))*32 + (xi1>>3))*32];
  float4* ob = (float4*)(out + ((size_t)blockIdx.x*256 + px)*32);
  #pragma unroll
  for (int j=0;j<8;j++){
    float4 va = pa[j], vb = pb[j], vc = pc[j], vd = pd[j];
    float4 r;
    r.x = wa*va.x + wb*vb.x + wc*vc.x + wd*vd.x;
    r.y = wa*va.y + wb*vb.y + wc*vc.y + wd*vd.y;
    r.z = wa*va.z + wb*vb.z + wc*vc.z + wd*vd.z;
    r.w = wa*va.w + wb*vb.w + wc*vc.w + wd*vd.w;
    if (j == 0) r.x = r0;                       // channel 0 = raw image sample
    r.x = (r.x >= 0.f) ? r.x : 0.1f*r.x;
    r.y = (r.y >= 0.f) ? r.y : 0.1f*r.y;
    r.z = (r.z >= 0.f) ? r.z : 0.1f*r.z;
    r.w = (r.w >= 0.f) ? r.w : 0.1f*r.w;
    ob[j] = r;
  }
}

// ================= launch =================
extern "C" void kernel_launch(void* const* d_in, const int* in_sizes, int n_in,
                              void* d_out, int out_size){
  const float* x     = (const float*)d_in[0];
  const float* c1k   = (const float*)d_in[1];
  const float* c1b   = (const float*)d_in[2];
  const float* c2k   = (const float*)d_in[3];
  const float* c2b   = (const float*)d_in[4];
  const float* c3k   = (const float*)d_in[5];
  const float* c3b   = (const float*)d_in[6];
  const float* gamma = (const float*)d_in[7];
  const float* beta  = (const float*)d_in[8];
  const float* mean  = (const float*)d_in[9];
  const float* var   = (const float*)d_in[10];
  const float* d1k   = (const float*)d_in[11];
  const float* d1b   = (const float*)d_in[12];
  const float* d2k   = (const float*)d_in[13];
  const float* d2b   = (const float*)d_in[14];
  const float* d3k   = (const float*)d_in[15];
  const float* d3b   = (const float*)d_in[16];
  float* out = (float*)d_out;

  k_conv1<<<1024, 256>>>(x, c1k, c1b);
  k_conv2<<<1024, 256>>>(c2k, c2b);
  k_conv3<<<512, 256>>>(c3k, c3b);
  k_d1<<<496, 256>>>(gamma, beta, mean, var, d1k, d1b, d2k, d2b, d3k, d3b);
  k_sample<<<4096, 256>>>(x, out);
}

// round 7
// speedup vs baseline: 2.1134x; 1.2323x over previous
#include <cuda_runtime.h>

#define BN_EPS 1e-3f
typedef unsigned long long ull;

// ---------------- scratch (device globals, no allocation) ----------------
// conv1 out, parity-split: [b][y(128)][parity(2)][xh(64)][8c]   (8 MB)
__device__ __align__(16) float g_a1[16*128*2*64*8];
// conv2 out, parity+cgroup split: [b][y(64)][cg(4)][parity(2)][xh(32)][4c]  (4 MB)
__device__ __align__(16) float g_a2[16*64*4*2*32*4];
// conv3 out, sampler layout: [b][y(32)][x(32)][32c] (slot0 = 0 pad, ch c at c+1)  (2 MB)
__device__ __align__(16) float g_xi[16*32*32*32];
// d1 partial sums: [b(16)][kc(124)][col(64)]
__device__ __align__(16) float g_part[16*124*64];
__device__ float g_theta[16*6];

#define FMA4(A, s, W) { A.x += (s)*(W).x; A.y += (s)*(W).y; A.z += (s)*(W).z; A.w += (s)*(W).w; }

__device__ __forceinline__ ull pack2(float lo, float hi){
  ull r; asm("mov.b64 %0, {%1,%2};" : "=l"(r) : "f"(lo), "f"(hi)); return r;
}
__device__ __forceinline__ void fma2(ull& acc, ull a, ull b){
  asm("fma.rn.f32x2 %0, %1, %2, %0;" : "+l"(acc) : "l"(a), "l"(b));
}
__device__ __forceinline__ float2 unpack2(ull v){
  float2 r; asm("mov.b64 {%0,%1}, %2;" : "=f"(r.x), "=f"(r.y) : "l"(v)); return r;
}

// ================= conv1 (1->8) + relu + maxpool2 =================
__global__ void __launch_bounds__(256) k_conv1(const float* __restrict__ x,
                        const float* __restrict__ w,
                        const float* __restrict__ bias){
  __shared__ float sw[72];
  __shared__ float sb[8];
  int t = threadIdx.x;
  if (t < 72) sw[t] = w[t];
  if (t < 8)  sb[t] = bias[t];
  __syncthreads();
  int id = blockIdx.x*256 + t;                 // 16*128*128 threads
  int px = id & 127, py = (id>>7)&127, bb = id>>14;
  const float* xb = x + bb*65536;
  float in[4][4];
  #pragma unroll
  for (int dy=0; dy<4; dy++){
    int iy = 2*py + dy - 1;
    #pragma unroll
    for (int dx=0; dx<4; dx++){
      int ix = 2*px + dx - 1;
      in[dy][dx] = (iy>=0 && iy<256 && ix>=0 && ix<256) ? xb[iy*256+ix] : 0.f;
    }
  }
  float acc[2][2][8];
  #pragma unroll
  for (int p=0;p<2;p++)
    #pragma unroll
    for (int q=0;q<2;q++)
      #pragma unroll
      for (int oc=0;oc<8;oc++) acc[p][q][oc]=0.f;
  #pragma unroll
  for (int ky=0;ky<3;ky++){
    #pragma unroll
    for (int kx=0;kx<3;kx++){
      float wv[8];
      #pragma unroll
      for (int oc=0;oc<8;oc++) wv[oc] = sw[(ky*3+kx)*8+oc];
      #pragma unroll
      for (int p=0;p<2;p++){
        #pragma unroll
        for (int q=0;q<2;q++){
          float v = in[p+ky][q+kx];
          #pragma unroll
          for (int oc=0;oc<8;oc++) acc[p][q][oc] += v*wv[oc];
        }
      }
    }
  }
  float o[8];
  #pragma unroll
  for (int oc=0;oc<8;oc++){
    float m = fmaxf(fmaxf(acc[0][0][oc],acc[0][1][oc]),
                    fmaxf(acc[1][0][oc],acc[1][1][oc]));
    o[oc] = fmaxf(m + sb[oc], 0.f);
  }
  int par = px & 1, xh = px >> 1;
  float4* dst = (float4*)&g_a1[(size_t)((((bb*128+py)*2+par)*64+xh))*8];
  dst[0] = make_float4(o[0],o[1],o[2],o[3]);
  dst[1] = make_float4(o[4],o[5],o[6],o[7]);
}

// ================= conv2 (8->16) + relu + maxpool2, 8 oc/thread =================
__global__ void __launch_bounds__(256) k_conv2(const float* __restrict__ w, const float* __restrict__ bias){
  __shared__ __align__(16) float sw[1152];     // [tap][ic(8)][oc(16)]
  __shared__ float sb[16];
  int t = threadIdx.x;
  for (int i=t; i<1152; i+=256) sw[i] = w[i];
  if (t < 16) sb[t] = bias[t];
  __syncthreads();
  int id = blockIdx.x*256 + t;                 // 2*16*64*64 = 131072 threads
  int px = id & 63, py = (id>>6)&63, bb = (id>>12)&15, ch = id>>16;   // ch 0..1
  ull acc[4][4];
  #pragma unroll
  for (int i=0;i<4;i++)
    #pragma unroll
    for (int j=0;j<4;j++) acc[i][j]=0ull;
  #pragma unroll
  for (int ky=0; ky<3; ky++){
    #pragma unroll
    for (int kx=0; kx<3; kx++){
      float4 pv[2][2][2];                      // [p][q][half]
      #pragma unroll
      for (int p=0;p<2;p++){
        #pragma unroll
        for (int q=0;q<2;q++){
          int e = p + ky - 1, d = q + kx - 1;
          int iy = 2*py + e;
          int par = d & 1, xh = px + (d >> 1);
          float4 lo = make_float4(0,0,0,0), hi = lo;
          if (iy>=0 && iy<128 && xh>=0 && xh<64){
            const float4* pp = (const float4*)&g_a1[(size_t)((((bb*128+iy)*2+par)*64+xh))*8];
            lo = pp[0]; hi = pp[1];
          }
          pv[p][q][0] = lo; pv[p][q][1] = hi;
        }
      }
      #pragma unroll
      for (int ic=0; ic<8; ic++){
        const ull* wp = (const ull*)&sw[((ky*3+kx)*8 + ic)*16 + ch*8];
        ull w0 = wp[0], w1 = wp[1], w2 = wp[2], w3 = wp[3];
        #pragma unroll
        for (int p=0;p<2;p++){
          #pragma unroll
          for (int q=0;q<2;q++){
            float s = ((const float*)&pv[p][q][ic>>2])[ic&3];
            ull s2 = pack2(s, s);
            int pos = p*2+q;
            fma2(acc[pos][0], s2, w0);
            fma2(acc[pos][1], s2, w1);
            fma2(acc[pos][2], s2, w2);
            fma2(acc[pos][3], s2, w3);
          }
        }
      }
    }
  }
  float o[8];
  #pragma unroll
  for (int u=0; u<4; u++){
    float2 a = unpack2(acc[0][u]), b2 = unpack2(acc[1][u]);
    float2 c = unpack2(acc[2][u]), d2 = unpack2(acc[3][u]);
    o[u*2+0] = fmaxf(fmaxf(fmaxf(a.x,b2.x),fmaxf(c.x,d2.x)) + sb[ch*8+u*2+0], 0.f);
    o[u*2+1] = fmaxf(fmaxf(fmaxf(a.y,b2.y),fmaxf(c.y,d2.y)) + sb[ch*8+u*2+1], 0.f);
  }
  int par = px & 1, xh = px >> 1;
  int cg0 = ch*2;
  *(float4*)&g_a2[(size_t)(((((bb*64+py)*4+cg0  )*2+par)*32+xh))*4] = make_float4(o[0],o[1],o[2],o[3]);
  *(float4*)&g_a2[(size_t)(((((bb*64+py)*4+cg0+1)*2+par)*32+xh))*4] = make_float4(o[4],o[5],o[6],o[7]);
}

// ================= conv3 (16->31) + relu + maxpool2, 8 oc/thread =================
__global__ void __launch_bounds__(256) k_conv3(const float* __restrict__ w, const float* __restrict__ bias){
  __shared__ __align__(16) float sw[4608];     // [tap][ic(16)][ocpad(32)]
  __shared__ float sb[32];
  int t = threadIdx.x;
  for (int i=t; i<4608; i+=256){
    int tap_ic = i >> 5, oc = i & 31;
    sw[i] = (oc < 31) ? w[tap_ic*31 + oc] : 0.f;
  }
  if (t < 32) sb[t] = (t < 31) ? bias[t] : 0.f;
  __syncthreads();
  int id = blockIdx.x*256 + t;                  // 4*16*32*32 = 65536 threads
  int px = id & 31, py = (id>>5)&31, bb = (id>>10)&15, ch = id>>14;   // ch 0..3
  ull acc[4][4];
  #pragma unroll
  for (int i=0;i<4;i++)
    #pragma unroll
    for (int j=0;j<4;j++) acc[i][j]=0ull;
  #pragma unroll
  for (int ky=0; ky<3; ky++){
    #pragma unroll
    for (int kx=0; kx<3; kx++){
      #pragma unroll
      for (int cg=0; cg<4; cg++){
        float4 pv[2][2];
        #pragma unroll
        for (int p=0;p<2;p++){
          #pragma unroll
          for (int q=0;q<2;q++){
            int e = p + ky - 1, d = q + kx - 1;
            int iy = 2*py + e;
            int par = d & 1, xh = px + (d >> 1);
            float4 v = make_float4(0,0,0,0);
            if (iy>=0 && iy<64 && xh>=0 && xh<32){
              v = *(const float4*)&g_a2[(size_t)(((((bb*64+iy)*4+cg)*2+par)*32+xh))*4];
            }
            pv[p][q] = v;
          }
        }
        #pragma unroll
        for (int l=0; l<4; l++){
          int ic = cg*4 + l;
          const ull* wp = (const ull*)&sw[((ky*3+kx)*16 + ic)*32 + ch*8];
          ull w0 = wp[0], w1 = wp[1], w2 = wp[2], w3 = wp[3];
          #pragma unroll
          for (int p=0;p<2;p++){
            #pragma unroll
            for (int q=0;q<2;q++){
              float s = ((const float*)&pv[p][q])[l];
              ull s2 = pack2(s, s);
              int pos = p*2+q;
              fma2(acc[pos][0], s2, w0);
              fma2(acc[pos][1], s2, w1);
              fma2(acc[pos][2], s2, w2);
              fma2(acc[pos][3], s2, w3);
            }
          }
        }
      }
    }
  }
  float mv[8];
  #pragma unroll
  for (int u=0; u<4; u++){
    float2 a = unpack2(acc[0][u]), b2 = unpack2(acc[1][u]);
    float2 c = unpack2(acc[2][u]), d2 = unpack2(acc[3][u]);
    mv[u*2+0] = fmaxf(fmaxf(fmaxf(a.x,b2.x),fmaxf(c.x,d2.x)) + sb[ch*8+u*2+0], 0.f);
    mv[u*2+1] = fmaxf(fmaxf(fmaxf(a.y,b2.y),fmaxf(c.y,d2.y)) + sb[ch*8+u*2+1], 0.f);
  }
  int pixbase = ((bb*32+py)*32+px)*32;
  if (ch == 0) g_xi[pixbase] = 0.f;             // channel-0 pad slot
  #pragma unroll
  for (int j=0;j<8;j++){
    int oc = ch*8 + j;
    if (oc < 31) g_xi[pixbase + 1 + oc] = mv[j];
  }
}

// ======= BN-fold + dense1 (31744->64): partials, no atomics, no tail =======
__global__ void __launch_bounds__(256) k_d1(
      const float* __restrict__ gamma, const float* __restrict__ beta,
      const float* __restrict__ mean,  const float* __restrict__ var,
      const float* __restrict__ d1k){
  __shared__ float sc[256], sh[256];
  __shared__ float sf[4][256];
  __shared__ float sred[4][16][64];
  int t  = threadIdx.x;
  int kc = blockIdx.x >> 2;                     // 0..123
  int bg = blockIdx.x & 3;                      // batches bg*4 .. bg*4+3
  int cb = kc * 256;
  {
    int i = cb + t;
    float scale = gamma[i] * rsqrtf(var[i] + BN_EPS);
    sc[t] = scale;
    sh[t] = beta[i] - mean[i]*scale;
  }
  __syncthreads();
  for (int idx=t; idx<1024; idx+=256){
    int bl = idx >> 8, f = idx & 255;
    int i = cb + f;
    int c = i % 31;
    int rest = i / 31;                          // = y*32 + x
    sf[bl][f] = g_xi[((bg*4+bl)*1024 + rest)*32 + 1 + c] * sc[f] + sh[f];
  }
  __syncthreads();
  int c4 = t & 15;                              // column group (4 cols)
  int fg = t >> 4;                              // 16 f-groups of 16 rows
  float4 a0 = make_float4(0,0,0,0), a1 = a0, a2 = a0, a3 = a0;
  {
    const float4* k4 = (const float4*)d1k + (size_t)(cb + fg*16)*16 + c4;
    const float* sfp = &sf[0][fg*16];
    #pragma unroll
    for (int j=0; j<16; j++){
      float4 wv = k4[j*16];
      float s0 = sfp[j], s1v = sfp[256+j], s2v = sfp[512+j], s3v = sfp[768+j];
      FMA4(a0, s0, wv);
      FMA4(a1, s1v, wv);
      FMA4(a2, s2v, wv);
      FMA4(a3, s3v, wv);
    }
  }
  *(float4*)&sred[0][fg][c4*4] = a0;
  *(float4*)&sred[1][fg][c4*4] = a1;
  *(float4*)&sred[2][fg][c4*4] = a2;
  *(float4*)&sred[3][fg][c4*4] = a3;
  __syncthreads();
  {
    int bl = t >> 6, col = t & 63;
    float s = 0.f;
    #pragma unroll
    for (int g=0; g<16; g++) s += sred[bl][g][col];
    g_part[((bg*4+bl)*124 + kc)*64 + col] = s;
  }
}

// ======= reduce partials + d1 bias/relu + d2 + d3 -> theta (16 blocks) =======
__global__ void __launch_bounds__(96) k_d23(
      const float* __restrict__ d1b,
      const float* __restrict__ d2k, const float* __restrict__ d2b,
      const float* __restrict__ d3k, const float* __restrict__ d3b){
  __shared__ float s1[64];
  __shared__ float s2[96];
  int b = blockIdx.x, t = threadIdx.x;          // 96 threads
  if (t < 64){
    const float* pp = &g_part[b*124*64 + t];
    float s = 0.f;
    #pragma unroll 4
    for (int kc=0; kc<124; kc++) s += pp[kc*64];
    s1[t] = fmaxf(s + d1b[t], 0.f);
  }
  __syncthreads();
  float a = d2b[t];
  #pragma unroll 8
  for (int k=0;k<64;k++) a += s1[k]*d2k[k*96+t];
  s2[t] = fmaxf(a, 0.f);
  __syncthreads();
  if (t < 6){
    float acc = d3b[t];
    #pragma unroll 8
    for (int k=0;k<96;k++) acc += s2[k]*d3k[k*6+t];
    g_theta[b*6+t] = acc;
  }
}

// ======= grid-gen + bilinear sampler + leaky relu, smem-staged stores =======
__global__ void __launch_bounds__(256) k_sample(const float* __restrict__ x, float* __restrict__ out){
  __shared__ float th[6];
  __shared__ __align__(16) float sres[256*36];  // 36 floats/pixel: pad for banks
  int b = blockIdx.x >> 8;
  int y = blockIdx.x & 255;
  int px = threadIdx.x;
  if (px < 6) th[px] = g_theta[b*6+px];
  __syncthreads();
  float gxn = ((float)px / 255.f)*2.f - 1.f;
  float gyn = ((float)y  / 255.f)*2.f - 1.f;
  float tgx = gxn*th[0] + gyn*th[3] + th[2];
  float tgy = gxn*th[1] + gyn*th[4] + th[5];
  float fx = 0.5f*((tgx + 1.f)*255.f);
  float fy = 0.5f*((tgy + 1.f)*255.f);
  float x0 = floorf(fx), x1 = x0 + 1.f;
  float y0 = floorf(fy), y1 = y0 + 1.f;
  x0 = fminf(fmaxf(x0,0.f),255.f);  x1 = fminf(fmaxf(x1,0.f),255.f);
  y0 = fminf(fmaxf(y0,0.f),255.f);  y1 = fminf(fmaxf(y1,0.f),255.f);
  float wa = (x1-fx)*(y1-fy);
  float wb = (x1-fx)*(fy-y0);
  float wc = (fx-x0)*(y1-fy);
  float wd = (fx-x0)*(fy-y0);
  int xi0=(int)x0, xi1=(int)x1, yi0=(int)y0, yi1=(int)y1;
  const float* xb = x + b*65536;
  float Ia = xb[yi0*256+xi0], Ib = xb[yi1*256+xi0];
  float Ic = xb[yi0*256+xi1], Id = xb[yi1*256+xi1];
  float r0 = wa*Ia + wb*Ib + wc*Ic + wd*Id;
  const float4* pa = (const float4*)&g_xi[((b*32 + (yi0>>3))*32 + (xi0>>3))*32];
  const float4* pb = (const float4*)&g_xi[((b*32 + (yi1>>3))*32 + (xi0>>3))*32];
  const float4* pc = (const float4*)&g_xi[((b*32 + (yi0>>3))*32 + (xi1>>3))*32];
  const float4* pd = (const float4*)&g_xi[((b*32 + (yi1>>3))*32 + (xi1>>3))*32];
  #pragma unroll
  for (int j=0;j<8;j++){
    float4 va = pa[j], vb = pb[j], vc = pc[j], vd = pd[j];
    float4 r;
    r.x = wa*va.x + wb*vb.x + wc*vc.x + wd*vd.x;
    r.y = wa*va.y + wb*vb.y + wc*vc.y + wd*vd.y;
    r.z = wa*va.z + wb*vb.z + wc*vc.z + wd*vd.z;
    r.w = wa*va.w + wb*vb.w + wc*vc.w + wd*vd.w;
    if (j == 0) r.x = r0;                       // channel 0 = raw image sample
    r.x = (r.x >= 0.f) ? r.x : 0.1f*r.x;
    r.y = (r.y >= 0.f) ? r.y : 0.1f*r.y;
    r.z = (r.z >= 0.f) ? r.z : 0.1f*r.z;
    r.w = (r.w >= 0.f) ? r.w : 0.1f*r.w;
    *(float4*)&sres[px*36 + j*4] = r;
  }
  __syncthreads();
  float4* o4 = (float4*)(out + (size_t)blockIdx.x*8192);
  #pragma unroll
  for (int it=0; it<8; it++){
    int v = it*256 + px;                        // linear float4 index 0..2047
    int p = v >> 3, c4 = v & 7;
    o4[v] = *(const float4*)&sres[p*36 + c4*4];
  }
}

// ================= launch =================
extern "C" void kernel_launch(void* const* d_in, const int* in_sizes, int n_in,
                              void* d_out, int out_size){
  const float* x     = (const float*)d_in[0];
  const float* c1k   = (const float*)d_in[1];
  const float* c1b   = (const float*)d_in[2];
  const float* c2k   = (const float*)d_in[3];
  const float* c2b   = (const float*)d_in[4];
  const float* c3k   = (const float*)d_in[5];
  const float* c3b   = (const float*)d_in[6];
  const float* gamma = (const float*)d_in[7];
  const float* beta  = (const float*)d_in[8];
  const float* mean  = (const float*)d_in[9];
  const float* var   = (const float*)d_in[10];
  const float* d1k   = (const float*)d_in[11];
  const float* d1b   = (const float*)d_in[12];
  const float* d2k   = (const float*)d_in[13];
  const float* d2b   = (const float*)d_in[14];
  const float* d3k   = (const float*)d_in[15];
  const float* d3b   = (const float*)d_in[16];
  float* out = (float*)d_out;

  k_conv1<<<1024, 256>>>(x, c1k, c1b);
  k_conv2<<<512, 256>>>(c2k, c2b);
  k_conv3<<<256, 256>>>(c3k, c3b);
  k_d1<<<496, 256>>>(gamma, beta, mean, var, d1k);
  k_d23<<<16, 96>>>(d1b, d2k, d2b, d3k, d3b);
  k_sample<<<4096, 256>>>(x, out);
}

// round 9
// speedup vs baseline: 2.6816x; 1.2689x over previous
#include <cuda_runtime.h>

#define BN_EPS 1e-3f
typedef unsigned long long ull;

// ---------------- scratch (device globals, no allocation) ----------------
// conv1 out: [b][y(128)][hf(2)][parity(2)][xh(64)][4c]   (8 MB) - 16B lane stride
__device__ __align__(16) float g_a1[16*128*2*2*64*4];
// conv2 out: [b][y(64)][cg(4)][parity(2)][xh(32)][4c]  (4 MB)
__device__ __align__(16) float g_a2[16*64*4*2*32*4];
// conv3 out, sampler layout: [b][y(32)][x(32)][32c] (slot0 = 0 pad, ch c at c+1)  (2 MB)
__device__ __align__(16) float g_xi[16*32*32*32];
// d1 partial sums: [b(16)][kc(124)][col(64)]
__device__ __align__(16) float g_part[16*124*64];
__device__ float g_theta[16*6];

#define FMA4(A, s, W) { A.x += (s)*(W).x; A.y += (s)*(W).y; A.z += (s)*(W).z; A.w += (s)*(W).w; }

__device__ __forceinline__ ull pack2(float lo, float hi){
  ull r; asm("mov.b64 %0, {%1,%2};" : "=l"(r) : "f"(lo), "f"(hi)); return r;
}
__device__ __forceinline__ void fma2(ull& acc, ull a, ull b){
  asm("fma.rn.f32x2 %0, %1, %2, %0;" : "+l"(acc) : "l"(a), "l"(b));
}
__device__ __forceinline__ float2 unpack2(ull v){
  float2 r; asm("mov.b64 {%0,%1}, %2;" : "=f"(r.x), "=f"(r.y) : "l"(v)); return r;
}
__device__ __forceinline__ float f4c(const float4& v, int i){
  return (i==0)?v.x:(i==1)?v.y:(i==2)?v.z:v.w;
}

// ================= conv1 (1->8) + relu + maxpool2, f32x2 =================
__global__ void __launch_bounds__(256) k_conv1(const float* __restrict__ x,
                        const float* __restrict__ w,
                        const float* __restrict__ bias){
  __shared__ __align__(16) float sw[72];
  __shared__ float sb[8];
  int t = threadIdx.x;
  if (t < 72) sw[t] = w[t];
  if (t < 8)  sb[t] = bias[t];
  __syncthreads();
  int id = blockIdx.x*256 + t;                 // 16*128*128 threads
  int px = id & 127, py = (id>>7)&127, bb = id>>14;
  const float* xb = x + bb*65536;
  float in[4][4];
  #pragma unroll
  for (int dy=0; dy<4; dy++){
    int iy = 2*py + dy - 1;
    #pragma unroll
    for (int dx=0; dx<4; dx++){
      int ix = 2*px + dx - 1;
      in[dy][dx] = (iy>=0 && iy<256 && ix>=0 && ix<256) ? xb[iy*256+ix] : 0.f;
    }
  }
  ull acc[2][2][4];
  #pragma unroll
  for (int p=0;p<2;p++)
    #pragma unroll
    for (int q=0;q<2;q++)
      #pragma unroll
      for (int u=0;u<4;u++) acc[p][q][u]=0ull;
  #pragma unroll
  for (int ky=0;ky<3;ky++){
    #pragma unroll
    for (int kx=0;kx<3;kx++){
      ulonglong2 wA = *(const ulonglong2*)&sw[(ky*3+kx)*8];
      ulonglong2 wB = *(const ulonglong2*)&sw[(ky*3+kx)*8+4];
      #pragma unroll
      for (int p=0;p<2;p++){
        #pragma unroll
        for (int q=0;q<2;q++){
          float s = in[p+ky][q+kx];
          ull s2 = pack2(s,s);
          fma2(acc[p][q][0], s2, wA.x);
          fma2(acc[p][q][1], s2, wA.y);
          fma2(acc[p][q][2], s2, wB.x);
          fma2(acc[p][q][3], s2, wB.y);
        }
      }
    }
  }
  float o[8];
  #pragma unroll
  for (int u=0;u<4;u++){
    float2 a = unpack2(acc[0][0][u]), b2 = unpack2(acc[0][1][u]);
    float2 c = unpack2(acc[1][0][u]), d2 = unpack2(acc[1][1][u]);
    o[u*2+0] = fmaxf(fmaxf(fmaxf(a.x,b2.x),fmaxf(c.x,d2.x)) + sb[u*2+0], 0.f);
    o[u*2+1] = fmaxf(fmaxf(fmaxf(a.y,b2.y),fmaxf(c.y,d2.y)) + sb[u*2+1], 0.f);
  }
  int par = px & 1, xh = px >> 1;
  *(float4*)&g_a1[(size_t)(((((bb*128+py)*2+0)*2+par)*64+xh))*4] = make_float4(o[0],o[1],o[2],o[3]);
  *(float4*)&g_a1[(size_t)(((((bb*128+py)*2+1)*2+par)*64+xh))*4] = make_float4(o[4],o[5],o[6],o[7]);
}

// ====== conv2 (8->16) + relu + maxpool2, row-wise load-once, 8 oc/thread ======
__global__ void __launch_bounds__(256) k_conv2(const float* __restrict__ w, const float* __restrict__ bias){
  __shared__ __align__(16) float sw[1152];     // [tap][ic(8)][oc(16)]
  __shared__ float sb[16];
  int t = threadIdx.x;
  for (int i=t; i<1152; i+=256) sw[i] = w[i];
  if (t < 16) sb[t] = bias[t];
  __syncthreads();
  int id = blockIdx.x*256 + t;                 // 2*16*64*64 = 131072 threads
  int px = id & 63, py = (id>>6)&63, bb = (id>>12)&15, ch = id>>16;   // ch 0..1
  ull acc[4][4];
  #pragma unroll
  for (int i=0;i<4;i++)
    #pragma unroll
    for (int j=0;j<4;j++) acc[i][j]=0ull;
  #pragma unroll
  for (int e=-1; e<=2; e++){
    int iy = 2*py + e;
    bool vy = (iy>=0 && iy<128);
    float4 lo[4], hi[4];
    #pragma unroll
    for (int dd=0; dd<4; dd++){
      int d = dd-1;
      int par = d & 1, xh = px + (d >> 1);
      lo[dd] = make_float4(0,0,0,0); hi[dd] = lo[dd];
      if (vy && xh>=0 && xh<64){
        lo[dd] = *(const float4*)&g_a1[(size_t)(((((bb*128+iy)*2+0)*2+par)*64+xh))*4];
        hi[dd] = *(const float4*)&g_a1[(size_t)(((((bb*128+iy)*2+1)*2+par)*64+xh))*4];
      }
    }
    #pragma unroll
    for (int ky=0; ky<3; ky++){
      int p = e - ky + 1;
      if (p < 0 || p > 1) continue;
      #pragma unroll
      for (int kx=0; kx<3; kx++){
        #pragma unroll
        for (int ic=0; ic<8; ic++){
          const float* wbase = &sw[((ky*3+kx)*8 + ic)*16 + ch*8];
          ulonglong2 wA = *(const ulonglong2*)wbase;
          ulonglong2 wB = *(const ulonglong2*)(wbase+4);
          #pragma unroll
          for (int qq=0; qq<2; qq++){
            int dd = kx + qq;                   // d = kx-1+qq, q = qq
            int pos = p*2 + qq;
            float s = (ic<4) ? f4c(lo[dd], ic) : f4c(hi[dd], ic-4);
            ull s2 = pack2(s,s);
            fma2(acc[pos][0], s2, wA.x);
            fma2(acc[pos][1], s2, wA.y);
            fma2(acc[pos][2], s2, wB.x);
            fma2(acc[pos][3], s2, wB.y);
          }
        }
      }
    }
  }
  float o[8];
  #pragma unroll
  for (int u=0; u<4; u++){
    float2 a = unpack2(acc[0][u]), b2 = unpack2(acc[1][u]);
    float2 c = unpack2(acc[2][u]), d2 = unpack2(acc[3][u]);
    o[u*2+0] = fmaxf(fmaxf(fmaxf(a.x,b2.x),fmaxf(c.x,d2.x)) + sb[ch*8+u*2+0], 0.f);
    o[u*2+1] = fmaxf(fmaxf(fmaxf(a.y,b2.y),fmaxf(c.y,d2.y)) + sb[ch*8+u*2+1], 0.f);
  }
  int par = px & 1, xh = px >> 1;
  int cg0 = ch*2;
  *(float4*)&g_a2[(size_t)(((((bb*64+py)*4+cg0  )*2+par)*32+xh))*4] = make_float4(o[0],o[1],o[2],o[3]);
  *(float4*)&g_a2[(size_t)(((((bb*64+py)*4+cg0+1)*2+par)*32+xh))*4] = make_float4(o[4],o[5],o[6],o[7]);
}

// ====== conv3 (16->31) + relu + maxpool2, row-wise load-once, 8 oc/thread ======
__global__ void __launch_bounds__(256) k_conv3(const float* __restrict__ w, const float* __restrict__ bias){
  __shared__ __align__(16) float sw[4608];     // [tap][ic(16)][ocpad(32)]
  __shared__ float sb[32];
  int t = threadIdx.x;
  for (int i=t; i<4608; i+=256){
    int tap_ic = i >> 5, oc = i & 31;
    sw[i] = (oc < 31) ? w[tap_ic*31 + oc] : 0.f;
  }
  if (t < 32) sb[t] = (t < 31) ? bias[t] : 0.f;
  __syncthreads();
  int id = blockIdx.x*256 + t;                  // 4*16*32*32 = 65536 threads
  int px = id & 31, py = (id>>5)&31, bb = (id>>10)&15, ch = id>>14;   // ch 0..3
  ull acc[4][4];
  #pragma unroll
  for (int i=0;i<4;i++)
    #pragma unroll
    for (int j=0;j<4;j++) acc[i][j]=0ull;
  #pragma unroll
  for (int e=-1; e<=2; e++){
    int iy = 2*py + e;
    bool vy = (iy>=0 && iy<64);
    float4 pv[4][4];                            // [dd][cg]
    #pragma unroll
    for (int dd=0; dd<4; dd++){
      int d = dd-1;
      int par = d & 1, xh = px + (d >> 1);
      bool v = vy && xh>=0 && xh<32;
      #pragma unroll
      for (int cg=0; cg<4; cg++){
        pv[dd][cg] = v ? *(const float4*)&g_a2[(size_t)(((((bb*64+iy)*4+cg)*2+par)*32+xh))*4]
                       : make_float4(0,0,0,0);
      }
    }
    #pragma unroll
    for (int ky=0; ky<3; ky++){
      int p = e - ky + 1;
      if (p < 0 || p > 1) continue;
      #pragma unroll
      for (int kx=0; kx<3; kx++){
        #pragma unroll
        for (int cg=0; cg<4; cg++){
          #pragma unroll
          for (int l=0; l<4; l++){
            int ic = cg*4 + l;
            const float* wbase = &sw[((ky*3+kx)*16 + ic)*32 + ch*8];
            ulonglong2 wA = *(const ulonglong2*)wbase;
            ulonglong2 wB = *(const ulonglong2*)(wbase+4);
            #pragma unroll
            for (int qq=0; qq<2; qq++){
              int dd = kx + qq;
              int pos = p*2 + qq;
              float s = f4c(pv[dd][cg], l);
              ull s2 = pack2(s,s);
              fma2(acc[pos][0], s2, wA.x);
              fma2(acc[pos][1], s2, wA.y);
              fma2(acc[pos][2], s2, wB.x);
              fma2(acc[pos][3], s2, wB.y);
            }
          }
        }
      }
    }
  }
  float mv[8];
  #pragma unroll
  for (int u=0; u<4; u++){
    float2 a = unpack2(acc[0][u]), b2 = unpack2(acc[1][u]);
    float2 c = unpack2(acc[2][u]), d2 = unpack2(acc[3][u]);
    mv[u*2+0] = fmaxf(fmaxf(fmaxf(a.x,b2.x),fmaxf(c.x,d2.x)) + sb[ch*8+u*2+0], 0.f);
    mv[u*2+1] = fmaxf(fmaxf(fmaxf(a.y,b2.y),fmaxf(c.y,d2.y)) + sb[ch*8+u*2+1], 0.f);
  }
  int pixbase = ((bb*32+py)*32+px)*32;
  if (ch == 0) g_xi[pixbase] = 0.f;             // channel-0 pad slot
  #pragma unroll
  for (int j=0;j<8;j++){
    int oc = ch*8 + j;
    if (oc < 31) g_xi[pixbase + 1 + oc] = mv[j];
  }
}

// ======= BN-fold + dense1 (31744->64): partials, no atomics =======
__global__ void __launch_bounds__(256) k_d1(
      const float* __restrict__ gamma, const float* __restrict__ beta,
      const float* __restrict__ mean,  const float* __restrict__ var,
      const float* __restrict__ d1k){
  __shared__ float sc[256], sh[256];
  __shared__ float sf[4][256];
  __shared__ float sred[4][16][64];
  int t  = threadIdx.x;
  int kc = blockIdx.x >> 2;                     // 0..123
  int bg = blockIdx.x & 3;                      // batches bg*4 .. bg*4+3
  int cb = kc * 256;
  {
    int i = cb + t;
    float scale = gamma[i] * rsqrtf(var[i] + BN_EPS);
    sc[t] = scale;
    sh[t] = beta[i] - mean[i]*scale;
  }
  __syncthreads();
  for (int idx=t; idx<1024; idx+=256){
    int bl = idx >> 8, f = idx & 255;
    int i = cb + f;
    int c = i % 31;
    int rest = i / 31;                          // = y*32 + x
    sf[bl][f] = g_xi[((bg*4+bl)*1024 + rest)*32 + 1 + c] * sc[f] + sh[f];
  }
  __syncthreads();
  int c4 = t & 15;                              // column group (4 cols)
  int fg = t >> 4;                              // 16 f-groups of 16 rows
  float4 a0 = make_float4(0,0,0,0), a1 = a0, a2 = a0, a3 = a0;
  {
    const float4* k4 = (const float4*)d1k + (size_t)(cb + fg*16)*16 + c4;
    const float* sfp = &sf[0][fg*16];
    #pragma unroll
    for (int j=0; j<16; j++){
      float4 wv = k4[j*16];
      float s0 = sfp[j], s1v = sfp[256+j], s2v = sfp[512+j], s3v = sfp[768+j];
      FMA4(a0, s0, wv);
      FMA4(a1, s1v, wv);
      FMA4(a2, s2v, wv);
      FMA4(a3, s3v, wv);
    }
  }
  *(float4*)&sred[0][fg][c4*4] = a0;
  *(float4*)&sred[1][fg][c4*4] = a1;
  *(float4*)&sred[2][fg][c4*4] = a2;
  *(float4*)&sred[3][fg][c4*4] = a3;
  __syncthreads();
  {
    int bl = t >> 6, col = t & 63;
    float s = 0.f;
    #pragma unroll
    for (int g=0; g<16; g++) s += sred[bl][g][col];
    g_part[((bg*4+bl)*124 + kc)*64 + col] = s;
  }
}

// ======= reduce partials + d1 bias/relu + d2 + d3 -> theta (16 blocks) =======
__global__ void __launch_bounds__(96) k_d23(
      const float* __restrict__ d1b,
      const float* __restrict__ d2k, const float* __restrict__ d2b,
      const float* __restrict__ d3k, const float* __restrict__ d3b){
  __shared__ float s1[64];
  __shared__ float s2[96];
  int b = blockIdx.x, t = threadIdx.x;          // 96 threads
  if (t < 64){
    const float* pp = &g_part[b*124*64 + t];
    float s = 0.f;
    #pragma unroll 4
    for (int kc=0; kc<124; kc++) s += pp[kc*64];
    s1[t] = fmaxf(s + d1b[t], 0.f);
  }
  __syncthreads();
  float a = d2b[t];
  #pragma unroll 8
  for (int k=0;k<64;k++) a += s1[k]*d2k[k*96+t];
  s2[t] = fmaxf(a, 0.f);
  __syncthreads();
  if (t < 6){
    float acc = d3b[t];
    #pragma unroll 8
    for (int k=0;k<96;k++) acc += s2[k]*d3k[k*6+t];
    g_theta[b*6+t] = acc;
  }
}

// ======= grid-gen + bilinear sampler + leaky relu =======
// Cell-dedup: the 4 bilinear taps hit the same 8x8 upsample cell for most
// pixels; combined weights (wa+wc etc.) are exact because the gathered
// channel vectors are identical. Skipped loads via branches.
__global__ void __launch_bounds__(256) k_sample(const float* __restrict__ x, float* __restrict__ out){
  __shared__ float th[6];
  __shared__ __align__(16) float sres[256*36];  // 36 floats/pixel: pad for banks
  int b = blockIdx.x >> 8;
  int y = blockIdx.x & 255;
  int px = threadIdx.x;
  if (px < 6) th[px] = g_theta[b*6+px];
  __syncthreads();
  float gxn = ((float)px / 255.f)*2.f - 1.f;
  float gyn = ((float)y  / 255.f)*2.f - 1.f;
  float tgx = gxn*th[0] + gyn*th[3] + th[2];
  float tgy = gxn*th[1] + gyn*th[4] + th[5];
  float fx = 0.5f*((tgx + 1.f)*255.f);
  float fy = 0.5f*((tgy + 1.f)*255.f);
  float x0 = floorf(fx), x1 = x0 + 1.f;
  float y0 = floorf(fy), y1 = y0 + 1.f;
  x0 = fminf(fmaxf(x0,0.f),255.f);  x1 = fminf(fmaxf(x1,0.f),255.f);
  y0 = fminf(fmaxf(y0,0.f),255.f);  y1 = fminf(fmaxf(y1,0.f),255.f);
  float wa = (x1-fx)*(y1-fy);
  float wb = (x1-fx)*(fy-y0);
  float wc = (fx-x0)*(y1-fy);
  float wd = (fx-x0)*(fy-y0);
  int xi0=(int)x0, xi1=(int)x1, yi0=(int)y0, yi1=(int)y1;
  const float* xb = x + b*65536;
  float Ia = xb[yi0*256+xi0], Ib = xb[yi1*256+xi0];
  float Ic = xb[yi0*256+xi1], Id = xb[yi1*256+xi1];
  float r0 = wa*Ia + wb*Ib + wc*Ic + wd*Id;

  int cxa = xi0>>3, cxb = xi1>>3, cya = yi0>>3, cyb = yi1>>3;
  bool sx = (cxa == cxb), sy = (cya == cyb);
  float WA=wa, WB=wb, WC=wc, WD=wd;
  if (sx){ WA += WC; WB += WD; }
  if (sy){ WA += WB; WC += WD; }
  float4 racc[8];
  {
    const float4* pa = (const float4*)&g_xi[((b*32 + cya)*32 + cxa)*32];
    #pragma unroll
    for (int j=0;j<8;j++){
      float4 v = pa[j];
      racc[j] = make_float4(WA*v.x, WA*v.y, WA*v.z, WA*v.w);
    }
  }
  if (!sy){
    const float4* pb = (const float4*)&g_xi[((b*32 + cyb)*32 + cxa)*32];
    #pragma unroll
    for (int j=0;j<8;j++){ float4 v = pb[j]; FMA4(racc[j], WB, v); }
  }
  if (!sx){
    const float4* pc = (const float4*)&g_xi[((b*32 + cya)*32 + cxb)*32];
    #pragma unroll
    for (int j=0;j<8;j++){ float4 v = pc[j]; FMA4(racc[j], WC, v); }
    if (!sy){
      const float4* pd = (const float4*)&g_xi[((b*32 + cyb)*32 + cxb)*32];
      #pragma unroll
      for (int j=0;j<8;j++){ float4 v = pd[j]; FMA4(racc[j], WD, v); }
    }
  }
  racc[0].x = r0;                               // channel 0 = raw image sample
  #pragma unroll
  for (int j=0;j<8;j++){
    float4 r = racc[j];
    r.x = (r.x >= 0.f) ? r.x : 0.1f*r.x;
    r.y = (r.y >= 0.f) ? r.y : 0.1f*r.y;
    r.z = (r.z >= 0.f) ? r.z : 0.1f*r.z;
    r.w = (r.w >= 0.f) ? r.w : 0.1f*r.w;
    *(float4*)&sres[px*36 + j*4] = r;
  }
  __syncthreads();
  float4* o4 = (float4*)(out + (size_t)blockIdx.x*8192);
  #pragma unroll
  for (int it=0; it<8; it++){
    int v = it*256 + px;                        // linear float4 index 0..2047
    int p = v >> 3, c4 = v & 7;
    __stcs(&o4[v], *(const float4*)&sres[p*36 + c4*4]);
  }
}

// ================= launch =================
extern "C" void kernel_launch(void* const* d_in, const int* in_sizes, int n_in,
                              void* d_out, int out_size){
  const float* x     = (const float*)d_in[0];
  const float* c1k   = (const float*)d_in[1];
  const float* c1b   = (const float*)d_in[2];
  const float* c2k   = (const float*)d_in[3];
  const float* c2b   = (const float*)d_in[4];
  const float* c3k   = (const float*)d_in[5];
  const float* c3b   = (const float*)d_in[6];
  const float* gamma = (const float*)d_in[7];
  const float* beta  = (const float*)d_in[8];
  const float* mean  = (const float*)d_in[9];
  const float* var   = (const float*)d_in[10];
  const float* d1k   = (const float*)d_in[11];
  const float* d1b   = (const float*)d_in[12];
  const float* d2k   = (const float*)d_in[13];
  const float* d2b   = (const float*)d_in[14];
  const float* d3k   = (const float*)d_in[15];
  const float* d3b   = (const float*)d_in[16];
  float* out = (float*)d_out;

  k_conv1<<<1024, 256>>>(x, c1k, c1b);
  k_conv2<<<512, 256>>>(c2k, c2b);
  k_conv3<<<256, 256>>>(c3k, c3b);
  k_d1<<<496, 256>>>(gamma, beta, mean, var, d1k);
  k_d23<<<16, 96>>>(d1b, d2k, d2b, d3k, d3b);
  k_sample<<<4096, 256>>>(x, out);
}